// round 15
// baseline (speedup 1.0000x reference)
#include <cuda_runtime.h>
#include <cuda_fp16.h>
#include <cstdint>
#include <math.h>

// fp32 normalized protos (staging), validity, compacted split images + LUT
__device__ __align__(16) float g_protoF[256 * 256];
__device__ int g_valid[256];
__device__ __align__(16) unsigned g_protoH2[8 * 4096];  // compacted: [ct][kp][cidx]
__device__ __align__(16) unsigned g_protoL2[8 * 4096];
__device__ int g_map[256];
__device__ int g_vcnt;

// ---- dist smem layout (4B units) ----
#define AS   260          // A tile row stride (16 kp rows x 260)
#define QS2  132          // Q tile row stride (16 kp rows x 132 px-u32)
#define DSS  269          // dS row stride (64 pixel rows x 269 proto cols)
#define OFF_A0  0
#define OFF_A1  8320      // 2*16*260
#define OFF_Q   16640     // 2 bufs x (QH 2112 + QL 2112)
#define QBUF    4224
#define SMEM_FLOATS 25088
#define SMEM_BYTES (SMEM_FLOATS * 4)   // 100.4 KB -> 2 CTAs/SM
// post-mainloop aliases
#define OFF_SQ  17216     // 16 x 128
#define OFF_QN  19264     // 128
#define OFF_RA  19392
#define OFF_RI  19648
#define OFF_RS  19904
#define OFF_RW  20160

// proto_kernel staging smem: 256 rows x 65 floats + 256 reduce
#define PSTRIDE 65
#define PROTO_SMEM_BYTES ((256 * PSTRIDE + 256) * 4)

__device__ __forceinline__ uint32_t s2u(const void* p) {
    uint32_t a;
    asm("{ .reg .u64 t; cvta.to.shared.u64 t, %1; cvt.u32.u64 %0, t; }"
        : "=r"(a) : "l"(p));
    return a;
}
__device__ __forceinline__ void cpasync16(uint32_t dst, const void* src) {
    size_t g = __cvta_generic_to_global(src);
    asm volatile("cp.async.cg.shared.global [%0], [%1], 16;"
                 :: "r"(dst), "l"(g) : "memory");
}
__device__ __forceinline__ uint32_t pack_h2(float a, float b) {
    __half_raw ra = (__half_raw)__float2half_rn(a);
    __half_raw rb = (__half_raw)__float2half_rn(b);
    return (uint32_t)ra.x | ((uint32_t)rb.x << 16);
}
__device__ __forceinline__ float h2f(float x) {
    return __half2float(__float2half_rn(x));
}
__device__ __forceinline__ void mma16(float* c, uint32_t a0, uint32_t a1,
                                      uint32_t a2, uint32_t a3,
                                      uint32_t b0, uint32_t b1) {
    asm volatile(
        "mma.sync.aligned.m16n8k16.row.col.f32.f16.f16.f32 "
        "{%0,%1,%2,%3}, {%4,%5,%6,%7}, {%8,%9}, {%0,%1,%2,%3};"
        : "+f"(c[0]), "+f"(c[1]), "+f"(c[2]), "+f"(c[3])
        : "r"(a0), "r"(a1), "r"(a2), "r"(a3), "r"(b0), "r"(b1));
}

// ---------------------------------------------------------------------------
// Kernel 1: prototypes -> normalized fp32 staging + validity
// Coalesced: stage 256ch x 64px block through smem (8-lane sector loads),
// then pool per-channel with the SAME pairwise summation order as before.
// ---------------------------------------------------------------------------
__global__ void proto_kernel(const float* __restrict__ sup_x,
                             const float* __restrict__ sup_y) {
    extern __shared__ float ps[];               // [256*65] staging + [256] reduce
    float* sh = ps + 256 * PSTRIDE;
    int p = blockIdx.x;
    int s = p >> 6, ij = p & 63, i = ij >> 3, j = ij & 7;
    int t = threadIdx.x;
    int lane8 = t & 7, grp = t >> 3;

    const float* base = sup_x + (size_t)s * 256 * 4096 + (i * 8) * 64 + j * 8;
#pragma unroll 8
    for (int r = 0; r < 64; r++) {
        int g = grp + r * 32;                   // g = c*8 + di
        int c = g >> 3, di = g & 7;
        ps[c * PSTRIDE + di * 8 + lane8] =
            base[(size_t)c * 4096 + di * 64 + lane8];
    }
    __syncthreads();

    int c = t;
    const float* row = ps + c * PSTRIDE;
    float sum = 0.f;
#pragma unroll
    for (int di = 0; di < 8; di++) {
        const float* r = row + di * 8;
        sum += ((r[0] + r[1]) + (r[2] + r[3])) + ((r[4] + r[5]) + (r[6] + r[7]));
    }
    float f = sum * (1.0f / 64.0f);

    sh[c] = f * f;
    __syncthreads();
    for (int st = 128; st > 0; st >>= 1) {
        if (c < st) sh[c] += sh[c + st];
        __syncthreads();
    }
    float inv = 1.0f / fmaxf(sqrtf(sh[0]), 1e-4f);
    g_protoF[p * 256 + c] = f * inv;
    __syncthreads();

    float m = 0.f;
    if (c < 64) {
        int di = c >> 3, dj = c & 7;
        float y = sup_y[(size_t)s * 4096 + (i * 8 + di) * 64 + (j * 8 + dj)];
        m = (y > 0.95f) ? 1.f : 0.f;
    }
    sh[c] = m;
    __syncthreads();
    for (int st = 128; st > 0; st >>= 1) {
        if (c < st) sh[c] += sh[c + st];
        __syncthreads();
    }
    if (c == 0) g_valid[p] = (sh[0] * (1.0f / 64.0f) > 0.5f) ? 1 : 0;
}

// ---------------------------------------------------------------------------
// Kernel 2: pack with inline scan (each block recomputes the 256-wide scan;
// cheaper than a separate launch) + proto_grid passthrough
// ---------------------------------------------------------------------------
__global__ void pack_kernel(const float* __restrict__ sup_y,
                            float* __restrict__ out) {
    __shared__ int sc[256];
    int p = blockIdx.x, t = threadIdx.x;
    sc[t] = g_valid[t];
    __syncthreads();
    for (int off = 1; off < 256; off <<= 1) {
        int add = (t >= off) ? sc[t - off] : 0;
        __syncthreads();
        sc[t] += add;
        __syncthreads();
    }
    if (p == 0 && t == 255) g_vcnt = sc[255];

    if (t < 64) {
        int idx = p * 64 + t;
        out[262144 + idx] = (sup_y[idx] > 0.95f) ? 1.f : 0.f;
    }
    if (g_valid[p]) {
        int ci = sc[p] - 1;
        if (t == 0) g_map[ci] = p;
        if (t < 128) {
            int ct = t >> 4, kp = t & 15;
            const float* src = g_protoF + p * 256;
            float v0 = src[ct * 32 + 2 * kp];
            float v1 = src[ct * 32 + 2 * kp + 1];
            g_protoH2[ct * 4096 + kp * 256 + ci] = pack_h2(v0, v1);
            g_protoL2[ct * 4096 + kp * 256 + ci] =
                pack_h2(v0 - h2f(v0), v1 - h2f(v1));
        }
    }
}

// ---------------------------------------------------------------------------
// Kernel 3: 3x fp16-split mma.sync(k16) over COMPACTED protos, 128-px tiles
// (byte-identical mainloop/epilogue to the 109 µs best)
// ---------------------------------------------------------------------------
__global__ void __launch_bounds__(256, 2)
dist_kernel(const float* __restrict__ qry, float* __restrict__ out) {
    extern __shared__ __align__(16) float sm[];
    float* SQ = sm + OFF_SQ;
    float* QN = sm + OFF_QN;
    float* RA = sm + OFF_RA;
    int*   RI = (int*)(sm + OFF_RI);
    float* RS = sm + OFF_RS;
    float* RW = sm + OFF_RW;

    int tid = threadIdx.x, w = tid >> 5, l = tid & 31;
    int wm = w & 1, wn = w >> 1;

    const int V = g_vcnt;
    const int nTiles = (V + 15) >> 4;
    const int V16 = nTiles << 4;
    int tmax = (nTiles + 1 - wm) >> 1;
    if (tmax > 4) tmax = 4;

    int b = blockIdx.x >> 5, n0 = (blockIdx.x & 31) << 7;
    const float* Qbase = qry + (size_t)b * 256 * 4096 + n0;

    float acc[4][4][4];
#pragma unroll
    for (int tm = 0; tm < 4; tm++)
#pragma unroll
        for (int tn = 0; tn < 4; tn++)
#pragma unroll
            for (int e = 0; e < 4; e++) acc[tm][tn][e] = 0.f;

    float4 qe0, qe1, qo0, qo1;
    float ssq8[8];
#pragma unroll
    for (int e = 0; e < 8; e++) ssq8[e] = 0.f;
    const int kp0 = tid >> 4, nf = tid & 15;
    const int ka = l & 3, ga = l >> 2;

#define Q_LOAD(ctv)                                                            \
    {                                                                          \
        const float* qc = Qbase + (size_t)((ctv) * 32 + 2 * kp0) * 4096 + nf * 8; \
        qe0 = *(const float4*)(qc);                                            \
        qe1 = *(const float4*)(qc + 4);                                        \
        qo0 = *(const float4*)(qc + 4096);                                     \
        qo1 = *(const float4*)(qc + 4100);                                     \
    }

#define SPLIT_STORE(QHdst, QLdst)                                              \
    {                                                                          \
        float ev[8] = {qe0.x, qe0.y, qe0.z, qe0.w, qe1.x, qe1.y, qe1.z, qe1.w};\
        float od[8] = {qo0.x, qo0.y, qo0.z, qo0.w, qo1.x, qo1.y, qo1.z, qo1.w};\
        uint32_t hq[8], lq[8];                                                 \
        _Pragma("unroll")                                                      \
        for (int e = 0; e < 8; e++) {                                          \
            hq[e] = pack_h2(ev[e], od[e]);                                     \
            lq[e] = pack_h2(ev[e] - h2f(ev[e]), od[e] - h2f(od[e]));           \
            ssq8[e] = fmaf(ev[e], ev[e], fmaf(od[e], od[e], ssq8[e]));         \
        }                                                                      \
        float* hb = (QHdst) + kp0 * QS2 + nf * 8;                              \
        float* lb = (QLdst) + kp0 * QS2 + nf * 8;                              \
        *(uint4*)hb       = make_uint4(hq[0], hq[1], hq[2], hq[3]);            \
        *(uint4*)(hb + 4) = make_uint4(hq[4], hq[5], hq[6], hq[7]);            \
        *(uint4*)lb       = make_uint4(lq[0], lq[1], lq[2], lq[3]);            \
        *(uint4*)(lb + 4) = make_uint4(lq[4], lq[5], lq[6], lq[7]);            \
    }

#define A_LOAD(dstbase, srcH, srcL)                                            \
    _Pragma("unroll")                                                          \
    for (int i = 0; i < 8; i++) {                                              \
        int seg = tid + i * 256;                                               \
        int mat = seg >> 10;                                                   \
        int row = (seg >> 6) & 15, col = (seg & 63) << 2;                      \
        if (col < V16) {                                                       \
            const unsigned* src = (mat ? (srcL) : (srcH)) + row * 256 + col;   \
            cpasync16(s2u((dstbase) + mat * (16 * AS) + row * AS + col), src); \
        }                                                                      \
    }

    // ---- prologue ----
    {
        A_LOAD(sm + OFF_A0, g_protoH2, g_protoL2)
        asm volatile("cp.async.commit_group;" ::: "memory");
        Q_LOAD(0)
        float* QHd = sm + OFF_Q;
        SPLIT_STORE(QHd, QHd + 2112)
        Q_LOAD(1)
    }

    for (int ct = 0; ct < 8; ct++) {
        int stg = ct & 1;
        float* AH = sm + (stg ? OFF_A1 : OFF_A0);
        float* AL = AH + 16 * AS;
        float* QH = sm + OFF_Q + stg * QBUF;
        float* QL = QH + 2112;

        asm volatile("cp.async.wait_group 0;" ::: "memory");
        __syncthreads();

        if (ct < 7) {
            float* AHn = sm + (stg ? OFF_A0 : OFF_A1);
            const unsigned* sH = g_protoH2 + (ct + 1) * 4096;
            const unsigned* sL = g_protoL2 + (ct + 1) * 4096;
            A_LOAD(AHn, sH, sL)
            asm volatile("cp.async.commit_group;" ::: "memory");

            float* QHd = sm + OFF_Q + (stg ^ 1) * QBUF;
            SPLIT_STORE(QHd, QHd + 2112)
            if (ct < 6) Q_LOAD(ct + 2)
        }

#pragma unroll
        for (int ks = 0; ks < 2; ks++) {
            uint32_t bh[4][2], bl[4][2];
            const int qb = (ks * 8 + ka) * QS2 + wn * 32 + ga;
#pragma unroll
            for (int tn = 0; tn < 4; tn++) {
                bh[tn][0] = __float_as_uint(QH[qb + tn * 8]);
                bh[tn][1] = __float_as_uint(QH[qb + tn * 8 + 4 * QS2]);
                bl[tn][0] = __float_as_uint(QL[qb + tn * 8]);
                bl[tn][1] = __float_as_uint(QL[qb + tn * 8 + 4 * QS2]);
            }
            const int ab = (ks * 8 + ka) * AS + wm * 16 + ga;
#pragma unroll
            for (int tm = 0; tm < 4; tm++) {
                if (tm < tmax) {
                    int a0i = ab + tm * 32;
                    uint32_t ah0 = __float_as_uint(AH[a0i]);
                    uint32_t ah1 = __float_as_uint(AH[a0i + 8]);
                    uint32_t ah2 = __float_as_uint(AH[a0i + 4 * AS]);
                    uint32_t ah3 = __float_as_uint(AH[a0i + 4 * AS + 8]);
                    uint32_t al0 = __float_as_uint(AL[a0i]);
                    uint32_t al1 = __float_as_uint(AL[a0i + 8]);
                    uint32_t al2 = __float_as_uint(AL[a0i + 4 * AS]);
                    uint32_t al3 = __float_as_uint(AL[a0i + 4 * AS + 8]);
#pragma unroll
                    for (int tn = 0; tn < 4; tn++)
                        mma16(acc[tm][tn], ah0, ah1, ah2, ah3, bh[tn][0], bh[tn][1]);
#pragma unroll
                    for (int tn = 0; tn < 4; tn++)
                        mma16(acc[tm][tn], ah0, ah1, ah2, ah3, bl[tn][0], bl[tn][1]);
#pragma unroll
                    for (int tn = 0; tn < 4; tn++)
                        mma16(acc[tm][tn], al0, al1, al2, al3, bh[tn][0], bh[tn][1]);
                }
            }
        }
    }

    __syncthreads();

    // ---- qnorm reduction (deterministic) ----
    {
        float* sq = SQ + kp0 * 128 + nf * 8;
        *(float4*)sq       = make_float4(ssq8[0], ssq8[1], ssq8[2], ssq8[3]);
        *(float4*)(sq + 4) = make_float4(ssq8[4], ssq8[5], ssq8[6], ssq8[7]);
    }
    __syncthreads();
    if (tid < 128) {
        float s = 0.f;
#pragma unroll
        for (int j = 0; j < 16; j++) s += SQ[j * 128 + tid];
        QN[tid] = 20.0f / fmaxf(sqrtf(s), 1e-4f);
    }
    __syncthreads();

    // ---- two-phase epilogue over 64-px halves, two-sweep softmax ----
    float* dS = sm;
    const float NEG = __int_as_float(0xff800000);
    const int L = (V + 3) >> 2;

    for (int ph = 0; ph < 2; ph++) {
        if ((wn >> 1) == ph) {
            int nbase = (wn & 1) * 32 + 2 * ka;
#pragma unroll
            for (int tm = 0; tm < 4; tm++) {
                if (tm < tmax) {
                    int r = (tm * 2 + wm) * 16 + ga;
#pragma unroll
                    for (int tn = 0; tn < 4; tn++) {
                        int n = nbase + tn * 8;
                        dS[n * DSS + r]           = acc[tm][tn][0];
                        dS[(n + 1) * DSS + r]     = acc[tm][tn][1];
                        dS[n * DSS + r + 8]       = acc[tm][tn][2];
                        dS[(n + 1) * DSS + r + 8] = acc[tm][tn][3];
                    }
                }
            }
        }
        __syncthreads();

        int q = tid >> 6, n = tid & 63;
        float scl = QN[ph * 64 + n];
        int c0 = q * L, c1 = min(c0 + L, V);
        const float* rowp = dS + n * DSS;

        float b0 = NEG, b1 = NEG, b2 = NEG, b3 = NEG;
        int i0 = 0, i1 = 0, i2 = 0, i3 = 0;
        int c = c0;
        for (; c + 4 <= c1; c += 4) {
            float d0 = rowp[c], d1 = rowp[c + 1], d2 = rowp[c + 2], d3 = rowp[c + 3];
            if (d0 > b0) { b0 = d0; i0 = c; }
            if (d1 > b1) { b1 = d1; i1 = c + 1; }
            if (d2 > b2) { b2 = d2; i2 = c + 2; }
            if (d3 > b3) { b3 = d3; i3 = c + 3; }
        }
        for (; c < c1; c++) {
            float d = rowp[c];
            if (d > b0) { b0 = d; i0 = c; }
        }
        float B = b0; int I = i0;
        if (b1 > B || (b1 == B && i1 < I)) { B = b1; I = i1; }
        if (b2 > B || (b2 == B && i2 < I)) { B = b2; I = i2; }
        if (b3 > B || (b3 == B && i3 < I)) { B = b3; I = i3; }
        float mx = B * scl;

        float s0 = 0.f, s1 = 0.f, s2 = 0.f, s3 = 0.f;
        float w0 = 0.f, w1 = 0.f, w2 = 0.f, w3 = 0.f;
        c = c0;
        for (; c + 4 <= c1; c += 4) {
            float d0 = rowp[c] * scl, d1 = rowp[c + 1] * scl;
            float d2 = rowp[c + 2] * scl, d3 = rowp[c + 3] * scl;
            float e0 = __expf(d0 - mx), e1 = __expf(d1 - mx);
            float e2 = __expf(d2 - mx), e3 = __expf(d3 - mx);
            s0 += e0; w0 = fmaf(e0, d0, w0);
            s1 += e1; w1 = fmaf(e1, d1, w1);
            s2 += e2; w2 = fmaf(e2, d2, w2);
            s3 += e3; w3 = fmaf(e3, d3, w3);
        }
        for (; c < c1; c++) {
            float d = rowp[c] * scl;
            float e = __expf(d - mx);
            s0 += e; w0 = fmaf(e, d, w0);
        }
        float se = (s0 + s1) + (s2 + s3);
        float ws = (w0 + w1) + (w2 + w3);

        RA[q * 64 + n] = (c1 > c0) ? mx : NEG;
        RI[q * 64 + n] = __ldg(&g_map[I]);
        RS[q * 64 + n] = se;
        RW[q * 64 + n] = ws;
        __syncthreads();

        if (tid < 64) {
            float Bm = NEG, SE = 0.f, WS = 0.f; int Im = 0;
#pragma unroll
            for (int qq = 0; qq < 4; qq++) {
                float bq = RA[qq * 64 + tid];
                float sq = RS[qq * 64 + tid], wq = RW[qq * 64 + tid];
                if (bq > Bm) {
                    float r = (Bm == NEG) ? 0.f : __expf(Bm - bq);
                    SE = SE * r + sq; WS = WS * r + wq;
                    Bm = bq; Im = RI[qq * 64 + tid];
                } else {
                    float r = (bq == NEG) ? 0.f : __expf(bq - Bm);
                    SE += sq * r; WS += wq * r;
                }
            }
            size_t o = (size_t)b * 4096 + n0 + ph * 64 + tid;
            out[o] = WS / SE;
            out[131072 + o] = (float)Im;
        }
        __syncthreads();
    }
}

extern "C" void kernel_launch(void* const* d_in, const int* in_sizes, int n_in,
                              void* d_out, int out_size) {
    const float* qry   = (const float*)d_in[0];
    const float* sup_x = (const float*)d_in[1];
    const float* sup_y = (const float*)d_in[2];
    float* out = (float*)d_out;

    cudaFuncSetAttribute(proto_kernel,
                         cudaFuncAttributeMaxDynamicSharedMemorySize,
                         PROTO_SMEM_BYTES);
    cudaFuncSetAttribute(dist_kernel,
                         cudaFuncAttributeMaxDynamicSharedMemorySize, SMEM_BYTES);

    proto_kernel<<<256, 256, PROTO_SMEM_BYTES>>>(sup_x, sup_y);
    pack_kernel<<<256, 256>>>(sup_y, out);
    dist_kernel<<<1024, 256, SMEM_BYTES>>>(qry, out);
}

// round 16
// speedup vs baseline: 1.0625x; 1.0625x over previous
#include <cuda_runtime.h>
#include <cuda_fp16.h>
#include <cstdint>
#include <math.h>

// fp32 normalized protos (staging), validity, compacted split images + LUT
__device__ __align__(16) float g_protoF[256 * 256];
__device__ int g_valid[256];
__device__ __align__(16) unsigned g_protoH2[8 * 4096];  // compacted: [ct][kp][cidx]
__device__ __align__(16) unsigned g_protoL2[8 * 4096];
__device__ int g_map[256];
__device__ int g_vcnt;

// ---- dist smem layout (4B units) ----
#define AS   260          // A tile row stride (16 kp rows x 260)
#define QS2  132          // Q tile row stride (16 kp rows x 132 px-u32)
#define DSS  269          // dS row stride (64 pixel rows x 269 proto cols)
#define OFF_A0  0
#define OFF_A1  8320      // 2*16*260
#define OFF_Q   16640     // 2 bufs x (QH 2112 + QL 2112)
#define QBUF    4224
#define SMEM_FLOATS 25088
#define SMEM_BYTES (SMEM_FLOATS * 4)   // 100.4 KB -> 2 CTAs/SM
// post-mainloop aliases
#define OFF_SQ  17216     // 16 x 128
#define OFF_QN  19264     // 128
#define OFF_RA  19392
#define OFF_RI  19648
#define OFF_RS  19904
#define OFF_RW  20160

__device__ __forceinline__ uint32_t s2u(const void* p) {
    uint32_t a;
    asm("{ .reg .u64 t; cvta.to.shared.u64 t, %1; cvt.u32.u64 %0, t; }"
        : "=r"(a) : "l"(p));
    return a;
}
__device__ __forceinline__ void cpasync16(uint32_t dst, const void* src) {
    size_t g = __cvta_generic_to_global(src);
    asm volatile("cp.async.cg.shared.global [%0], [%1], 16;"
                 :: "r"(dst), "l"(g) : "memory");
}
__device__ __forceinline__ uint32_t pack_h2(float a, float b) {
    __half2 h = __floats2half2_rn(a, b);
    return *reinterpret_cast<uint32_t*>(&h);
}
__device__ __forceinline__ float h2f(float x) {
    return __half2float(__float2half_rn(x));
}
__device__ __forceinline__ void mma16(float* c, uint32_t a0, uint32_t a1,
                                      uint32_t a2, uint32_t a3,
                                      uint32_t b0, uint32_t b1) {
    asm volatile(
        "mma.sync.aligned.m16n8k16.row.col.f32.f16.f16.f32 "
        "{%0,%1,%2,%3}, {%4,%5,%6,%7}, {%8,%9}, {%0,%1,%2,%3};"
        : "+f"(c[0]), "+f"(c[1]), "+f"(c[2]), "+f"(c[3])
        : "r"(a0), "r"(a1), "r"(a2), "r"(a3), "r"(b0), "r"(b1));
}

// ---------------------------------------------------------------------------
// Kernel 1: prototypes -> normalized fp32 staging + validity (proven 10us)
// ---------------------------------------------------------------------------
__global__ void proto_kernel(const float* __restrict__ sup_x,
                             const float* __restrict__ sup_y) {
    __shared__ float sh[256];
    int p = blockIdx.x;
    int s = p >> 6, ij = p & 63, i = ij >> 3, j = ij & 7;
    int c = threadIdx.x;

    const float* base = sup_x + (((size_t)(s * 256 + c)) * 64 + i * 8) * 64 + j * 8;
    float sum = 0.f;
#pragma unroll
    for (int di = 0; di < 8; di++) {
        const float4* r = (const float4*)(base + di * 64);
        float4 a = r[0], b4 = r[1];
        sum += ((a.x + a.y) + (a.z + a.w)) + ((b4.x + b4.y) + (b4.z + b4.w));
    }
    float f = sum * (1.0f / 64.0f);

    sh[c] = f * f;
    __syncthreads();
    for (int st = 128; st > 0; st >>= 1) {
        if (c < st) sh[c] += sh[c + st];
        __syncthreads();
    }
    float inv = 1.0f / fmaxf(sqrtf(sh[0]), 1e-4f);
    g_protoF[p * 256 + c] = f * inv;
    __syncthreads();

    float m = 0.f;
    if (c < 64) {
        int di = c >> 3, dj = c & 7;
        float y = sup_y[(size_t)s * 4096 + (i * 8 + di) * 64 + (j * 8 + dj)];
        m = (y > 0.95f) ? 1.f : 0.f;
    }
    sh[c] = m;
    __syncthreads();
    for (int st = 128; st > 0; st >>= 1) {
        if (c < st) sh[c] += sh[c + st];
        __syncthreads();
    }
    if (c == 0) g_valid[p] = (sh[0] * (1.0f / 64.0f) > 0.5f) ? 1 : 0;
}

// ---------------------------------------------------------------------------
// Kernel 2: pack with inline scan (proven) + proto_grid passthrough
// ---------------------------------------------------------------------------
__global__ void pack_kernel(const float* __restrict__ sup_y,
                            float* __restrict__ out) {
    __shared__ int sc[256];
    int p = blockIdx.x, t = threadIdx.x;
    sc[t] = g_valid[t];
    __syncthreads();
    for (int off = 1; off < 256; off <<= 1) {
        int add = (t >= off) ? sc[t - off] : 0;
        __syncthreads();
        sc[t] += add;
        __syncthreads();
    }
    if (p == 0 && t == 255) g_vcnt = sc[255];

    if (t < 64) {
        int idx = p * 64 + t;
        out[262144 + idx] = (sup_y[idx] > 0.95f) ? 1.f : 0.f;
    }
    if (g_valid[p]) {
        int ci = sc[p] - 1;
        if (t == 0) g_map[ci] = p;
        if (t < 128) {
            int ct = t >> 4, kp = t & 15;
            const float* src = g_protoF + p * 256;
            float v0 = src[ct * 32 + 2 * kp];
            float v1 = src[ct * 32 + 2 * kp + 1];
            g_protoH2[ct * 4096 + kp * 256 + ci] = pack_h2(v0, v1);
            g_protoL2[ct * 4096 + kp * 256 + ci] =
                pack_h2(v0 - h2f(v0), v1 - h2f(v1));
        }
    }
}

// ---------------------------------------------------------------------------
// Kernel 3: 3x fp16-split mma.sync(k16) over COMPACTED protos, 128-px tiles
// mainloop/epilogue math bitwise-identical to the 109 us best;
// SPLIT_STORE uses dual-convert F2FP.PACK (same rn values, fewer insts).
// ---------------------------------------------------------------------------
__global__ void __launch_bounds__(256, 2)
dist_kernel(const float* __restrict__ qry, float* __restrict__ out) {
    extern __shared__ __align__(16) float sm[];
    float* SQ = sm + OFF_SQ;
    float* QN = sm + OFF_QN;
    float* RA = sm + OFF_RA;
    int*   RI = (int*)(sm + OFF_RI);
    float* RS = sm + OFF_RS;
    float* RW = sm + OFF_RW;

    int tid = threadIdx.x, w = tid >> 5, l = tid & 31;
    int wm = w & 1, wn = w >> 1;

    const int V = g_vcnt;
    const int nTiles = (V + 15) >> 4;
    const int V16 = nTiles << 4;
    int tmax = (nTiles + 1 - wm) >> 1;
    if (tmax > 4) tmax = 4;

    int b = blockIdx.x >> 5, n0 = (blockIdx.x & 31) << 7;
    const float* Qbase = qry + (size_t)b * 256 * 4096 + n0;

    float acc[4][4][4];
#pragma unroll
    for (int tm = 0; tm < 4; tm++)
#pragma unroll
        for (int tn = 0; tn < 4; tn++)
#pragma unroll
            for (int e = 0; e < 4; e++) acc[tm][tn][e] = 0.f;

    float4 qe0, qe1, qo0, qo1;
    float ssq8[8];
#pragma unroll
    for (int e = 0; e < 8; e++) ssq8[e] = 0.f;
    const int kp0 = tid >> 4, nf = tid & 15;
    const int ka = l & 3, ga = l >> 2;

#define Q_LOAD(ctv)                                                            \
    {                                                                          \
        const float* qc = Qbase + (size_t)((ctv) * 32 + 2 * kp0) * 4096 + nf * 8; \
        qe0 = *(const float4*)(qc);                                            \
        qe1 = *(const float4*)(qc + 4);                                        \
        qo0 = *(const float4*)(qc + 4096);                                     \
        qo1 = *(const float4*)(qc + 4100);                                     \
    }

#define SPLIT_STORE(QHdst, QLdst)                                              \
    {                                                                          \
        float ev[8] = {qe0.x, qe0.y, qe0.z, qe0.w, qe1.x, qe1.y, qe1.z, qe1.w};\
        float od[8] = {qo0.x, qo0.y, qo0.z, qo0.w, qo1.x, qo1.y, qo1.z, qo1.w};\
        uint32_t hq[8], lq[8];                                                 \
        _Pragma("unroll")                                                      \
        for (int e = 0; e < 8; e++) {                                          \
            __half2 hh = __floats2half2_rn(ev[e], od[e]);                      \
            hq[e] = *reinterpret_cast<uint32_t*>(&hh);                         \
            float2 bk = __half22float2(hh);                                    \
            __half2 ll = __floats2half2_rn(ev[e] - bk.x, od[e] - bk.y);        \
            lq[e] = *reinterpret_cast<uint32_t*>(&ll);                         \
            ssq8[e] = fmaf(ev[e], ev[e], fmaf(od[e], od[e], ssq8[e]));         \
        }                                                                      \
        float* hb = (QHdst) + kp0 * QS2 + nf * 8;                              \
        float* lb = (QLdst) + kp0 * QS2 + nf * 8;                              \
        *(uint4*)hb       = make_uint4(hq[0], hq[1], hq[2], hq[3]);            \
        *(uint4*)(hb + 4) = make_uint4(hq[4], hq[5], hq[6], hq[7]);            \
        *(uint4*)lb       = make_uint4(lq[0], lq[1], lq[2], lq[3]);            \
        *(uint4*)(lb + 4) = make_uint4(lq[4], lq[5], lq[6], lq[7]);            \
    }

#define A_LOAD(dstbase, srcH, srcL)                                            \
    _Pragma("unroll")                                                          \
    for (int i = 0; i < 8; i++) {                                              \
        int seg = tid + i * 256;                                               \
        int mat = seg >> 10;                                                   \
        int row = (seg >> 6) & 15, col = (seg & 63) << 2;                      \
        if (col < V16) {                                                       \
            const unsigned* src = (mat ? (srcL) : (srcH)) + row * 256 + col;   \
            cpasync16(s2u((dstbase) + mat * (16 * AS) + row * AS + col), src); \
        }                                                                      \
    }

    // ---- prologue ----
    {
        A_LOAD(sm + OFF_A0, g_protoH2, g_protoL2)
        asm volatile("cp.async.commit_group;" ::: "memory");
        Q_LOAD(0)
        float* QHd = sm + OFF_Q;
        SPLIT_STORE(QHd, QHd + 2112)
        Q_LOAD(1)
    }

    for (int ct = 0; ct < 8; ct++) {
        int stg = ct & 1;
        float* AH = sm + (stg ? OFF_A1 : OFF_A0);
        float* AL = AH + 16 * AS;
        float* QH = sm + OFF_Q + stg * QBUF;
        float* QL = QH + 2112;

        asm volatile("cp.async.wait_group 0;" ::: "memory");
        __syncthreads();

        if (ct < 7) {
            float* AHn = sm + (stg ? OFF_A0 : OFF_A1);
            const unsigned* sH = g_protoH2 + (ct + 1) * 4096;
            const unsigned* sL = g_protoL2 + (ct + 1) * 4096;
            A_LOAD(AHn, sH, sL)
            asm volatile("cp.async.commit_group;" ::: "memory");

            float* QHd = sm + OFF_Q + (stg ^ 1) * QBUF;
            SPLIT_STORE(QHd, QHd + 2112)
            if (ct < 6) Q_LOAD(ct + 2)
        }

#pragma unroll
        for (int ks = 0; ks < 2; ks++) {
            uint32_t bh[4][2], bl[4][2];
            const int qb = (ks * 8 + ka) * QS2 + wn * 32 + ga;
#pragma unroll
            for (int tn = 0; tn < 4; tn++) {
                bh[tn][0] = __float_as_uint(QH[qb + tn * 8]);
                bh[tn][1] = __float_as_uint(QH[qb + tn * 8 + 4 * QS2]);
                bl[tn][0] = __float_as_uint(QL[qb + tn * 8]);
                bl[tn][1] = __float_as_uint(QL[qb + tn * 8 + 4 * QS2]);
            }
            const int ab = (ks * 8 + ka) * AS + wm * 16 + ga;
#pragma unroll
            for (int tm = 0; tm < 4; tm++) {
                if (tm < tmax) {
                    int a0i = ab + tm * 32;
                    uint32_t ah0 = __float_as_uint(AH[a0i]);
                    uint32_t ah1 = __float_as_uint(AH[a0i + 8]);
                    uint32_t ah2 = __float_as_uint(AH[a0i + 4 * AS]);
                    uint32_t ah3 = __float_as_uint(AH[a0i + 4 * AS + 8]);
                    uint32_t al0 = __float_as_uint(AL[a0i]);
                    uint32_t al1 = __float_as_uint(AL[a0i + 8]);
                    uint32_t al2 = __float_as_uint(AL[a0i + 4 * AS]);
                    uint32_t al3 = __float_as_uint(AL[a0i + 4 * AS + 8]);
#pragma unroll
                    for (int tn = 0; tn < 4; tn++)
                        mma16(acc[tm][tn], ah0, ah1, ah2, ah3, bh[tn][0], bh[tn][1]);
#pragma unroll
                    for (int tn = 0; tn < 4; tn++)
                        mma16(acc[tm][tn], ah0, ah1, ah2, ah3, bl[tn][0], bl[tn][1]);
#pragma unroll
                    for (int tn = 0; tn < 4; tn++)
                        mma16(acc[tm][tn], al0, al1, al2, al3, bh[tn][0], bh[tn][1]);
                }
            }
        }
    }

    __syncthreads();

    // ---- qnorm reduction (deterministic) ----
    {
        float* sq = SQ + kp0 * 128 + nf * 8;
        *(float4*)sq       = make_float4(ssq8[0], ssq8[1], ssq8[2], ssq8[3]);
        *(float4*)(sq + 4) = make_float4(ssq8[4], ssq8[5], ssq8[6], ssq8[7]);
    }
    __syncthreads();
    if (tid < 128) {
        float s = 0.f;
#pragma unroll
        for (int j = 0; j < 16; j++) s += SQ[j * 128 + tid];
        QN[tid] = 20.0f / fmaxf(sqrtf(s), 1e-4f);
    }
    __syncthreads();

    // ---- two-phase epilogue over 64-px halves, two-sweep softmax ----
    float* dS = sm;
    const float NEG = __int_as_float(0xff800000);
    const int L = (V + 3) >> 2;

    for (int ph = 0; ph < 2; ph++) {
        if ((wn >> 1) == ph) {
            int nbase = (wn & 1) * 32 + 2 * ka;
#pragma unroll
            for (int tm = 0; tm < 4; tm++) {
                if (tm < tmax) {
                    int r = (tm * 2 + wm) * 16 + ga;
#pragma unroll
                    for (int tn = 0; tn < 4; tn++) {
                        int n = nbase + tn * 8;
                        dS[n * DSS + r]           = acc[tm][tn][0];
                        dS[(n + 1) * DSS + r]     = acc[tm][tn][1];
                        dS[n * DSS + r + 8]       = acc[tm][tn][2];
                        dS[(n + 1) * DSS + r + 8] = acc[tm][tn][3];
                    }
                }
            }
        }
        __syncthreads();

        int q = tid >> 6, n = tid & 63;
        float scl = QN[ph * 64 + n];
        int c0 = q * L, c1 = min(c0 + L, V);
        const float* rowp = dS + n * DSS;

        float b0 = NEG, b1 = NEG, b2 = NEG, b3 = NEG;
        int i0 = 0, i1 = 0, i2 = 0, i3 = 0;
        int c = c0;
        for (; c + 4 <= c1; c += 4) {
            float d0 = rowp[c], d1 = rowp[c + 1], d2 = rowp[c + 2], d3 = rowp[c + 3];
            if (d0 > b0) { b0 = d0; i0 = c; }
            if (d1 > b1) { b1 = d1; i1 = c + 1; }
            if (d2 > b2) { b2 = d2; i2 = c + 2; }
            if (d3 > b3) { b3 = d3; i3 = c + 3; }
        }
        for (; c < c1; c++) {
            float d = rowp[c];
            if (d > b0) { b0 = d; i0 = c; }
        }
        float B = b0; int I = i0;
        if (b1 > B || (b1 == B && i1 < I)) { B = b1; I = i1; }
        if (b2 > B || (b2 == B && i2 < I)) { B = b2; I = i2; }
        if (b3 > B || (b3 == B && i3 < I)) { B = b3; I = i3; }
        float mx = B * scl;

        float s0 = 0.f, s1 = 0.f, s2 = 0.f, s3 = 0.f;
        float w0 = 0.f, w1 = 0.f, w2 = 0.f, w3 = 0.f;
        c = c0;
        for (; c + 4 <= c1; c += 4) {
            float d0 = rowp[c] * scl, d1 = rowp[c + 1] * scl;
            float d2 = rowp[c + 2] * scl, d3 = rowp[c + 3] * scl;
            float e0 = __expf(d0 - mx), e1 = __expf(d1 - mx);
            float e2 = __expf(d2 - mx), e3 = __expf(d3 - mx);
            s0 += e0; w0 = fmaf(e0, d0, w0);
            s1 += e1; w1 = fmaf(e1, d1, w1);
            s2 += e2; w2 = fmaf(e2, d2, w2);
            s3 += e3; w3 = fmaf(e3, d3, w3);
        }
        for (; c < c1; c++) {
            float d = rowp[c] * scl;
            float e = __expf(d - mx);
            s0 += e; w0 = fmaf(e, d, w0);
        }
        float se = (s0 + s1) + (s2 + s3);
        float ws = (w0 + w1) + (w2 + w3);

        RA[q * 64 + n] = (c1 > c0) ? mx : NEG;
        RI[q * 64 + n] = __ldg(&g_map[I]);
        RS[q * 64 + n] = se;
        RW[q * 64 + n] = ws;
        __syncthreads();

        if (tid < 64) {
            float Bm = NEG, SE = 0.f, WS = 0.f; int Im = 0;
#pragma unroll
            for (int qq = 0; qq < 4; qq++) {
                float bq = RA[qq * 64 + tid];
                float sq = RS[qq * 64 + tid], wq = RW[qq * 64 + tid];
                if (bq > Bm) {
                    float r = (Bm == NEG) ? 0.f : __expf(Bm - bq);
                    SE = SE * r + sq; WS = WS * r + wq;
                    Bm = bq; Im = RI[qq * 64 + tid];
                } else {
                    float r = (bq == NEG) ? 0.f : __expf(bq - Bm);
                    SE += sq * r; WS += wq * r;
                }
            }
            size_t o = (size_t)b * 4096 + n0 + ph * 64 + tid;
            out[o] = WS / SE;
            out[131072 + o] = (float)Im;
        }
        __syncthreads();
    }
}

extern "C" void kernel_launch(void* const* d_in, const int* in_sizes, int n_in,
                              void* d_out, int out_size) {
    const float* qry   = (const float*)d_in[0];
    const float* sup_x = (const float*)d_in[1];
    const float* sup_y = (const float*)d_in[2];
    float* out = (float*)d_out;

    cudaFuncSetAttribute(dist_kernel,
                         cudaFuncAttributeMaxDynamicSharedMemorySize, SMEM_BYTES);

    proto_kernel<<<256, 256>>>(sup_x, sup_y);
    pack_kernel<<<256, 256>>>(sup_y, out);
    dist_kernel<<<1024, 256, SMEM_BYTES>>>(qry, out);
}

// round 17
// speedup vs baseline: 1.0749x; 1.0117x over previous
#include <cuda_runtime.h>
#include <cuda_fp16.h>
#include <cstdint>
#include <math.h>

// fp32 normalized protos (staging), validity, compacted split images + LUT
__device__ __align__(16) float g_protoF[256 * 256];
__device__ int g_valid[256];
__device__ __align__(16) unsigned g_protoH2[8 * 4096];  // compacted: [ct][kp][cidx]
__device__ __align__(16) unsigned g_protoL2[8 * 4096];
__device__ int g_map[256];
__device__ int g_vcnt;

// ---- dist smem layout (4B units) ----
#define AS   260          // A tile row stride (16 kp rows x 260)
#define QS2  132          // Q tile row stride (16 kp rows x 132 px-u32)
#define DSS  269          // dS row stride (64 pixel rows x 269 proto cols)
#define OFF_A0  0
#define OFF_A1  8320      // 2*16*260
#define OFF_Q   16640     // 2 bufs x (QH 2112 + QL 2112)
#define QBUF    4224
#define SMEM_FLOATS 25088
#define SMEM_BYTES (SMEM_FLOATS * 4)   // 100.4 KB -> 2 CTAs/SM
// post-mainloop aliases
#define OFF_SQ  17216     // 16 x 128
#define OFF_QN  19264     // 128
#define OFF_RA  19392
#define OFF_RI  19648
#define OFF_RS  19904
#define OFF_RW  20160

__device__ __forceinline__ uint32_t s2u(const void* p) {
    uint32_t a;
    asm("{ .reg .u64 t; cvta.to.shared.u64 t, %1; cvt.u32.u64 %0, t; }"
        : "=r"(a) : "l"(p));
    return a;
}
__device__ __forceinline__ void cpasync16(uint32_t dst, const void* src) {
    size_t g = __cvta_generic_to_global(src);
    asm volatile("cp.async.cg.shared.global [%0], [%1], 16;"
                 :: "r"(dst), "l"(g) : "memory");
}
__device__ __forceinline__ uint32_t pack_h2(float a, float b) {
    __half_raw ra = (__half_raw)__float2half_rn(a);
    __half_raw rb = (__half_raw)__float2half_rn(b);
    return (uint32_t)ra.x | ((uint32_t)rb.x << 16);
}
__device__ __forceinline__ float h2f(float x) {
    return __half2float(__float2half_rn(x));
}
__device__ __forceinline__ void mma16(float* c, uint32_t a0, uint32_t a1,
                                      uint32_t a2, uint32_t a3,
                                      uint32_t b0, uint32_t b1) {
    asm volatile(
        "mma.sync.aligned.m16n8k16.row.col.f32.f16.f16.f32 "
        "{%0,%1,%2,%3}, {%4,%5,%6,%7}, {%8,%9}, {%0,%1,%2,%3};"
        : "+f"(c[0]), "+f"(c[1]), "+f"(c[2]), "+f"(c[3])
        : "r"(a0), "r"(a1), "r"(a2), "r"(a3), "r"(b0), "r"(b1));
}

// ---------------------------------------------------------------------------
// Kernel 1: prototypes -> normalized fp32 staging + validity (proven 10us)
// ---------------------------------------------------------------------------
__global__ void proto_kernel(const float* __restrict__ sup_x,
                             const float* __restrict__ sup_y) {
    __shared__ float sh[256];
    int p = blockIdx.x;
    int s = p >> 6, ij = p & 63, i = ij >> 3, j = ij & 7;
    int c = threadIdx.x;

    const float* base = sup_x + (((size_t)(s * 256 + c)) * 64 + i * 8) * 64 + j * 8;
    float sum = 0.f;
#pragma unroll
    for (int di = 0; di < 8; di++) {
        const float4* r = (const float4*)(base + di * 64);
        float4 a = r[0], b4 = r[1];
        sum += ((a.x + a.y) + (a.z + a.w)) + ((b4.x + b4.y) + (b4.z + b4.w));
    }
    float f = sum * (1.0f / 64.0f);

    sh[c] = f * f;
    __syncthreads();
    for (int st = 128; st > 0; st >>= 1) {
        if (c < st) sh[c] += sh[c + st];
        __syncthreads();
    }
    float inv = 1.0f / fmaxf(sqrtf(sh[0]), 1e-4f);
    g_protoF[p * 256 + c] = f * inv;
    __syncthreads();

    float m = 0.f;
    if (c < 64) {
        int di = c >> 3, dj = c & 7;
        float y = sup_y[(size_t)s * 4096 + (i * 8 + di) * 64 + (j * 8 + dj)];
        m = (y > 0.95f) ? 1.f : 0.f;
    }
    sh[c] = m;
    __syncthreads();
    for (int st = 128; st > 0; st >>= 1) {
        if (c < st) sh[c] += sh[c + st];
        __syncthreads();
    }
    if (c == 0) g_valid[p] = (sh[0] * (1.0f / 64.0f) > 0.5f) ? 1 : 0;
}

// ---------------------------------------------------------------------------
// Kernel 2: pack with inline scan (proven) + proto_grid passthrough
// ---------------------------------------------------------------------------
__global__ void pack_kernel(const float* __restrict__ sup_y,
                            float* __restrict__ out) {
    __shared__ int sc[256];
    int p = blockIdx.x, t = threadIdx.x;
    sc[t] = g_valid[t];
    __syncthreads();
    for (int off = 1; off < 256; off <<= 1) {
        int add = (t >= off) ? sc[t - off] : 0;
        __syncthreads();
        sc[t] += add;
        __syncthreads();
    }
    if (p == 0 && t == 255) g_vcnt = sc[255];

    if (t < 64) {
        int idx = p * 64 + t;
        out[262144 + idx] = (sup_y[idx] > 0.95f) ? 1.f : 0.f;
    }
    if (g_valid[p]) {
        int ci = sc[p] - 1;
        if (t == 0) g_map[ci] = p;
        if (t < 128) {
            int ct = t >> 4, kp = t & 15;
            const float* src = g_protoF + p * 256;
            float v0 = src[ct * 32 + 2 * kp];
            float v1 = src[ct * 32 + 2 * kp + 1];
            g_protoH2[ct * 4096 + kp * 256 + ci] = pack_h2(v0, v1);
            g_protoL2[ct * 4096 + kp * 256 + ci] =
                pack_h2(v0 - h2f(v0), v1 - h2f(v1));
        }
    }
}

// ---------------------------------------------------------------------------
// Kernel 3: 3x fp16-split mma.sync(k16) over COMPACTED protos, 128-px tiles.
// Intra-chunk software pipeline: BAR -> MMA(ks=0) -> next-chunk prep ->
// MMA(ks=1). Prep no longer barrier-aligned => HMMA pipe fills immediately.
// All arithmetic bitwise-identical to the 109 us best.
// ---------------------------------------------------------------------------
__global__ void __launch_bounds__(256, 2)
dist_kernel(const float* __restrict__ qry, float* __restrict__ out) {
    extern __shared__ __align__(16) float sm[];
    float* SQ = sm + OFF_SQ;
    float* QN = sm + OFF_QN;
    float* RA = sm + OFF_RA;
    int*   RI = (int*)(sm + OFF_RI);
    float* RS = sm + OFF_RS;
    float* RW = sm + OFF_RW;

    int tid = threadIdx.x, w = tid >> 5, l = tid & 31;
    int wm = w & 1, wn = w >> 1;

    const int V = g_vcnt;
    const int nTiles = (V + 15) >> 4;
    const int V16 = nTiles << 4;
    int tmax = (nTiles + 1 - wm) >> 1;
    if (tmax > 4) tmax = 4;

    int b = blockIdx.x >> 5, n0 = (blockIdx.x & 31) << 7;
    const float* Qbase = qry + (size_t)b * 256 * 4096 + n0;

    float acc[4][4][4];
#pragma unroll
    for (int tm = 0; tm < 4; tm++)
#pragma unroll
        for (int tn = 0; tn < 4; tn++)
#pragma unroll
            for (int e = 0; e < 4; e++) acc[tm][tn][e] = 0.f;

    float4 qe0, qe1, qo0, qo1;
    float ssq8[8];
#pragma unroll
    for (int e = 0; e < 8; e++) ssq8[e] = 0.f;
    const int kp0 = tid >> 4, nf = tid & 15;
    const int ka = l & 3, ga = l >> 2;

#define Q_LOAD(ctv)                                                            \
    {                                                                          \
        const float* qc = Qbase + (size_t)((ctv) * 32 + 2 * kp0) * 4096 + nf * 8; \
        qe0 = *(const float4*)(qc);                                            \
        qe1 = *(const float4*)(qc + 4);                                        \
        qo0 = *(const float4*)(qc + 4096);                                     \
        qo1 = *(const float4*)(qc + 4100);                                     \
    }

#define SPLIT_STORE(QHdst, QLdst)                                              \
    {                                                                          \
        float ev[8] = {qe0.x, qe0.y, qe0.z, qe0.w, qe1.x, qe1.y, qe1.z, qe1.w};\
        float od[8] = {qo0.x, qo0.y, qo0.z, qo0.w, qo1.x, qo1.y, qo1.z, qo1.w};\
        uint32_t hq[8], lq[8];                                                 \
        _Pragma("unroll")                                                      \
        for (int e = 0; e < 8; e++) {                                          \
            hq[e] = pack_h2(ev[e], od[e]);                                     \
            lq[e] = pack_h2(ev[e] - h2f(ev[e]), od[e] - h2f(od[e]));           \
            ssq8[e] = fmaf(ev[e], ev[e], fmaf(od[e], od[e], ssq8[e]));         \
        }                                                                      \
        float* hb = (QHdst) + kp0 * QS2 + nf * 8;                              \
        float* lb = (QLdst) + kp0 * QS2 + nf * 8;                              \
        *(uint4*)hb       = make_uint4(hq[0], hq[1], hq[2], hq[3]);            \
        *(uint4*)(hb + 4) = make_uint4(hq[4], hq[5], hq[6], hq[7]);            \
        *(uint4*)lb       = make_uint4(lq[0], lq[1], lq[2], lq[3]);            \
        *(uint4*)(lb + 4) = make_uint4(lq[4], lq[5], lq[6], lq[7]);            \
    }

#define A_LOAD(dstbase, srcH, srcL)                                            \
    _Pragma("unroll")                                                          \
    for (int i = 0; i < 8; i++) {                                              \
        int seg = tid + i * 256;                                               \
        int mat = seg >> 10;                                                   \
        int row = (seg >> 6) & 15, col = (seg & 63) << 2;                      \
        if (col < V16) {                                                       \
            const unsigned* src = (mat ? (srcL) : (srcH)) + row * 256 + col;   \
            cpasync16(s2u((dstbase) + mat * (16 * AS) + row * AS + col), src); \
        }                                                                      \
    }

#define MMA_KS(ksv)                                                            \
    {                                                                          \
        uint32_t bh[4][2], bl[4][2];                                           \
        const int qb = ((ksv) * 8 + ka) * QS2 + wn * 32 + ga;                  \
        _Pragma("unroll")                                                      \
        for (int tn = 0; tn < 4; tn++) {                                       \
            bh[tn][0] = __float_as_uint(QH[qb + tn * 8]);                      \
            bh[tn][1] = __float_as_uint(QH[qb + tn * 8 + 4 * QS2]);            \
            bl[tn][0] = __float_as_uint(QL[qb + tn * 8]);                      \
            bl[tn][1] = __float_as_uint(QL[qb + tn * 8 + 4 * QS2]);            \
        }                                                                      \
        const int ab = ((ksv) * 8 + ka) * AS + wm * 16 + ga;                   \
        _Pragma("unroll")                                                      \
        for (int tm = 0; tm < 4; tm++) {                                       \
            if (tm < tmax) {                                                   \
                int a0i = ab + tm * 32;                                        \
                uint32_t ah0 = __float_as_uint(AH[a0i]);                       \
                uint32_t ah1 = __float_as_uint(AH[a0i + 8]);                   \
                uint32_t ah2 = __float_as_uint(AH[a0i + 4 * AS]);              \
                uint32_t ah3 = __float_as_uint(AH[a0i + 4 * AS + 8]);          \
                uint32_t al0 = __float_as_uint(AL[a0i]);                       \
                uint32_t al1 = __float_as_uint(AL[a0i + 8]);                   \
                uint32_t al2 = __float_as_uint(AL[a0i + 4 * AS]);              \
                uint32_t al3 = __float_as_uint(AL[a0i + 4 * AS + 8]);          \
                _Pragma("unroll")                                              \
                for (int tn = 0; tn < 4; tn++)                                 \
                    mma16(acc[tm][tn], ah0, ah1, ah2, ah3, bh[tn][0], bh[tn][1]); \
                _Pragma("unroll")                                              \
                for (int tn = 0; tn < 4; tn++)                                 \
                    mma16(acc[tm][tn], ah0, ah1, ah2, ah3, bl[tn][0], bl[tn][1]); \
                _Pragma("unroll")                                              \
                for (int tn = 0; tn < 4; tn++)                                 \
                    mma16(acc[tm][tn], al0, al1, al2, al3, bh[tn][0], bh[tn][1]); \
            }                                                                  \
        }                                                                      \
    }

    // ---- prologue ----
    {
        A_LOAD(sm + OFF_A0, g_protoH2, g_protoL2)
        asm volatile("cp.async.commit_group;" ::: "memory");
        Q_LOAD(0)
        float* QHd = sm + OFF_Q;
        SPLIT_STORE(QHd, QHd + 2112)
        Q_LOAD(1)
    }

    for (int ct = 0; ct < 8; ct++) {
        int stg = ct & 1;
        float* AH = sm + (stg ? OFF_A1 : OFF_A0);
        float* AL = AH + 16 * AS;
        float* QH = sm + OFF_Q + stg * QBUF;
        float* QL = QH + 2112;

        asm volatile("cp.async.wait_group 0;" ::: "memory");
        __syncthreads();

        // ks=0 MMAs first: tensor pipe fills immediately after the barrier
        MMA_KS(0)

        // next-chunk prep, de-aligned from the barrier (hides under HMMAs)
        if (ct < 7) {
            float* AHn = sm + (stg ? OFF_A0 : OFF_A1);
            const unsigned* sH = g_protoH2 + (ct + 1) * 4096;
            const unsigned* sL = g_protoL2 + (ct + 1) * 4096;
            A_LOAD(AHn, sH, sL)
            asm volatile("cp.async.commit_group;" ::: "memory");

            float* QHd = sm + OFF_Q + (stg ^ 1) * QBUF;
            SPLIT_STORE(QHd, QHd + 2112)
            if (ct < 6) Q_LOAD(ct + 2)
        }

        // ks=1 MMAs
        MMA_KS(1)
    }

    __syncthreads();

    // ---- qnorm reduction (deterministic) ----
    {
        float* sq = SQ + kp0 * 128 + nf * 8;
        *(float4*)sq       = make_float4(ssq8[0], ssq8[1], ssq8[2], ssq8[3]);
        *(float4*)(sq + 4) = make_float4(ssq8[4], ssq8[5], ssq8[6], ssq8[7]);
    }
    __syncthreads();
    if (tid < 128) {
        float s = 0.f;
#pragma unroll
        for (int j = 0; j < 16; j++) s += SQ[j * 128 + tid];
        QN[tid] = 20.0f / fmaxf(sqrtf(s), 1e-4f);
    }
    __syncthreads();

    // ---- two-phase epilogue over 64-px halves, two-sweep softmax ----
    float* dS = sm;
    const float NEG = __int_as_float(0xff800000);
    const int L = (V + 3) >> 2;

    for (int ph = 0; ph < 2; ph++) {
        if ((wn >> 1) == ph) {
            int nbase = (wn & 1) * 32 + 2 * ka;
#pragma unroll
            for (int tm = 0; tm < 4; tm++) {
                if (tm < tmax) {
                    int r = (tm * 2 + wm) * 16 + ga;
#pragma unroll
                    for (int tn = 0; tn < 4; tn++) {
                        int n = nbase + tn * 8;
                        dS[n * DSS + r]           = acc[tm][tn][0];
                        dS[(n + 1) * DSS + r]     = acc[tm][tn][1];
                        dS[n * DSS + r + 8]       = acc[tm][tn][2];
                        dS[(n + 1) * DSS + r + 8] = acc[tm][tn][3];
                    }
                }
            }
        }
        __syncthreads();

        int q = tid >> 6, n = tid & 63;
        float scl = QN[ph * 64 + n];
        int c0 = q * L, c1 = min(c0 + L, V);
        const float* rowp = dS + n * DSS;

        float b0 = NEG, b1 = NEG, b2 = NEG, b3 = NEG;
        int i0 = 0, i1 = 0, i2 = 0, i3 = 0;
        int c = c0;
        for (; c + 4 <= c1; c += 4) {
            float d0 = rowp[c], d1 = rowp[c + 1], d2 = rowp[c + 2], d3 = rowp[c + 3];
            if (d0 > b0) { b0 = d0; i0 = c; }
            if (d1 > b1) { b1 = d1; i1 = c + 1; }
            if (d2 > b2) { b2 = d2; i2 = c + 2; }
            if (d3 > b3) { b3 = d3; i3 = c + 3; }
        }
        for (; c < c1; c++) {
            float d = rowp[c];
            if (d > b0) { b0 = d; i0 = c; }
        }
        float B = b0; int I = i0;
        if (b1 > B || (b1 == B && i1 < I)) { B = b1; I = i1; }
        if (b2 > B || (b2 == B && i2 < I)) { B = b2; I = i2; }
        if (b3 > B || (b3 == B && i3 < I)) { B = b3; I = i3; }
        float mx = B * scl;

        float s0 = 0.f, s1 = 0.f, s2 = 0.f, s3 = 0.f;
        float w0 = 0.f, w1 = 0.f, w2 = 0.f, w3 = 0.f;
        c = c0;
        for (; c + 4 <= c1; c += 4) {
            float d0 = rowp[c] * scl, d1 = rowp[c + 1] * scl;
            float d2 = rowp[c + 2] * scl, d3 = rowp[c + 3] * scl;
            float e0 = __expf(d0 - mx), e1 = __expf(d1 - mx);
            float e2 = __expf(d2 - mx), e3 = __expf(d3 - mx);
            s0 += e0; w0 = fmaf(e0, d0, w0);
            s1 += e1; w1 = fmaf(e1, d1, w1);
            s2 += e2; w2 = fmaf(e2, d2, w2);
            s3 += e3; w3 = fmaf(e3, d3, w3);
        }
        for (; c < c1; c++) {
            float d = rowp[c] * scl;
            float e = __expf(d - mx);
            s0 += e; w0 = fmaf(e, d, w0);
        }
        float se = (s0 + s1) + (s2 + s3);
        float ws = (w0 + w1) + (w2 + w3);

        RA[q * 64 + n] = (c1 > c0) ? mx : NEG;
        RI[q * 64 + n] = __ldg(&g_map[I]);
        RS[q * 64 + n] = se;
        RW[q * 64 + n] = ws;
        __syncthreads();

        if (tid < 64) {
            float Bm = NEG, SE = 0.f, WS = 0.f; int Im = 0;
#pragma unroll
            for (int qq = 0; qq < 4; qq++) {
                float bq = RA[qq * 64 + tid];
                float sq = RS[qq * 64 + tid], wq = RW[qq * 64 + tid];
                if (bq > Bm) {
                    float r = (Bm == NEG) ? 0.f : __expf(Bm - bq);
                    SE = SE * r + sq; WS = WS * r + wq;
                    Bm = bq; Im = RI[qq * 64 + tid];
                } else {
                    float r = (bq == NEG) ? 0.f : __expf(bq - Bm);
                    SE += sq * r; WS += wq * r;
                }
            }
            size_t o = (size_t)b * 4096 + n0 + ph * 64 + tid;
            out[o] = WS / SE;
            out[131072 + o] = (float)Im;
        }
        __syncthreads();
    }
}

extern "C" void kernel_launch(void* const* d_in, const int* in_sizes, int n_in,
                              void* d_out, int out_size) {
    const float* qry   = (const float*)d_in[0];
    const float* sup_x = (const float*)d_in[1];
    const float* sup_y = (const float*)d_in[2];
    float* out = (float*)d_out;

    cudaFuncSetAttribute(dist_kernel,
                         cudaFuncAttributeMaxDynamicSharedMemorySize, SMEM_BYTES);

    proto_kernel<<<256, 256>>>(sup_x, sup_y);
    pack_kernel<<<256, 256>>>(sup_y, out);
    dist_kernel<<<1024, 256, SMEM_BYTES>>>(qry, out);
}